// round 2
// baseline (speedup 1.0000x reference)
#include <cuda_runtime.h>
#include <math.h>

#define Bsz 32
#define TE  128
#define TD  64
#define Ee  256
#define Hh  256
#define Vv  32000
#define H3  (3*Hh)

// ---------------- device scratch (no allocs allowed) ----------------
__device__ float g_gi_f[Bsz*TE*H3];        // encoder fwd input proj (incl bi)
__device__ float g_gi_b[Bsz*TE*H3];        // encoder bwd input proj
__device__ float g_gi_demb[Bsz*TD*H3];     // decoder embedding part of input proj (incl bi_d)
__device__ float g_encoded[Bsz*TE*2*Hh];   // [B,TE,2H]
__device__ float g_outs[Bsz*TD*Hh];        // decoder hidden outputs
__device__ float g_hstate[2][2][Bsz*Hh];   // [dir][parity][B*H]
__device__ float g_hdec[2][Bsz*Hh];        // [parity]
__device__ float g_ctx[2][Bsz*2*Hh];       // [parity]
__device__ int   g_lastidx[Bsz];
__device__ float g_WhT[2][Hh*H3];          // transposed recurrent weights [k][3H]
__device__ float g_WdT[(3*Hh)*H3];         // unified decoder K=768 (512 ctx + 256 h) x [3H]
__device__ float g_W2T[Hh*2*Hh];           // [256 k][512 j]

// ---------------- init: sizes/last index, zero states ----------------
__global__ void init_kernel(const int* __restrict__ enc_in) {
    int tid = threadIdx.x;
    if (tid < Bsz) {
        int cnt = 0;
        for (int t = 0; t < TE; ++t) cnt += (enc_in[tid*TE + t] > 0) ? 1 : 0;
        int tt = cnt - 1; if (tt < 0) tt += TE;   // mimic JAX wraparound
        g_lastidx[tid] = tid*TE + tt;
    }
    for (int i = tid; i < 2*2*Bsz*Hh; i += blockDim.x) ((float*)g_hstate)[i] = 0.f;
    for (int i = tid; i < 2*Bsz*Hh;  i += blockDim.x) ((float*)g_hdec)[i]  = 0.f;
    for (int i = tid; i < 2*Bsz*2*Hh;i += blockDim.x) ((float*)g_ctx)[i]   = 0.f;
}

// ---------------- weight transposes (coalesced recurrent loads) ------
__global__ void transpose_wh(const float* __restrict__ Wh, int dir) {
    int idx = blockIdx.x*blockDim.x + threadIdx.x;   // over H*3H
    if (idx >= Hh*H3) return;
    int k = idx / H3, jj = idx % H3;
    g_WhT[dir][idx] = Wh[jj*Hh + k];
}
__global__ void transpose_wd(const float* __restrict__ Wi_d, const float* __restrict__ Wh_d) {
    int idx = blockIdx.x*blockDim.x + threadIdx.x;   // over 768*768
    if (idx >= 3*Hh*H3) return;
    int k = idx / H3, jj = idx % H3;
    g_WdT[idx] = (k < 2*Hh) ? Wi_d[jj*(Ee + 2*Hh) + k] : Wh_d[jj*Hh + (k - 2*Hh)];
}
__global__ void transpose_w2(const float* __restrict__ W2_w) {
    int idx = blockIdx.x*blockDim.x + threadIdx.x;   // over 256*512
    if (idx >= Hh*2*Hh) return;
    int k = idx / (2*Hh), jj = idx % (2*Hh);
    g_W2T[idx] = W2_w[jj*Hh + k];
}

// ---------------- generic fp32 GEMM: C = gatherA @ B^T + bias --------
// A row m = A + (gidx?gidx[m]:m)*lda ; B[n,k] = Bm[n*ldb + boff + k]
__global__ __launch_bounds__(256) void sgemm_tn(
    const float* __restrict__ A, const int* __restrict__ gidx, int lda,
    const float* __restrict__ Bm, int ldb, int boff,
    const float* __restrict__ bias, float* __restrict__ C, int ldc,
    int M, int N, int K)
{
    __shared__ float As[16][132];
    __shared__ float Bs[16][68];
    int tid = threadIdx.x;
    int ty = tid >> 4, tx = tid & 15;
    int m0 = blockIdx.y * 128, n0 = blockIdx.x * 64;
    float acc[8][4];
    #pragma unroll
    for (int i = 0; i < 8; ++i)
        #pragma unroll
        for (int j = 0; j < 4; ++j) acc[i][j] = 0.f;

    for (int k0 = 0; k0 < K; k0 += 16) {
        #pragma unroll
        for (int i = 0; i < 8; ++i) {
            int idx = tid + i*256;
            int kk = idx & 15, mm = idx >> 4;
            int mg = m0 + mm;
            float v = 0.f;
            if (mg < M) {
                int row = gidx ? gidx[mg] : mg;
                v = A[(long)row*lda + k0 + kk];
            }
            As[kk][mm] = v;
        }
        #pragma unroll
        for (int i = 0; i < 4; ++i) {
            int idx = tid + i*256;
            int kk = idx & 15, nn = idx >> 4;
            int ng = n0 + nn;
            Bs[kk][nn] = (ng < N) ? Bm[(long)ng*ldb + boff + k0 + kk] : 0.f;
        }
        __syncthreads();
        #pragma unroll
        for (int kk = 0; kk < 16; ++kk) {
            float a[8], bb[4];
            #pragma unroll
            for (int i = 0; i < 8; ++i) a[i] = As[kk][ty*8 + i];
            #pragma unroll
            for (int j = 0; j < 4; ++j) bb[j] = Bs[kk][tx*4 + j];
            #pragma unroll
            for (int i = 0; i < 8; ++i)
                #pragma unroll
                for (int j = 0; j < 4; ++j) acc[i][j] += a[i]*bb[j];
        }
        __syncthreads();
    }
    #pragma unroll
    for (int i = 0; i < 8; ++i) {
        int mg = m0 + ty*8 + i;
        if (mg >= M) continue;
        #pragma unroll
        for (int j = 0; j < 4; ++j) {
            int ng = n0 + tx*4 + j;
            if (ng < N) C[(long)mg*ldc + ng] = acc[i][j] + (bias ? bias[ng] : 0.f);
        }
    }
}

// ---------------- encoder GRU step (both directions per launch) ------
// grid 512 = dir(2) x b(32) x jc(8); 128 thr = tj(32) x ks(4)
__global__ __launch_bounds__(128) void enc_step(
    const float* __restrict__ bh_f, const float* __restrict__ bh_b, int s, int pb)
{
    int bx = blockIdx.x;
    int dir = bx & 1;
    int b   = (bx >> 1) & 31;
    int jc  = bx >> 6;
    int tid = threadIdx.x;
    int tj = tid & 31, ks = tid >> 5;
    int j = jc*32 + tj;
    int tt = dir ? (TE - 1 - s) : s;
    const float* bh   = dir ? bh_b : bh_f;
    const float* WhT  = g_WhT[dir];
    const float* hsrc = g_hstate[dir][pb] + b*Hh;
    float*       hdst = g_hstate[dir][pb ^ 1] + b*Hh;
    const float* gi   = (dir ? g_gi_b : g_gi_f) + (b*TE + tt)*H3;

    __shared__ float hs[Hh];
    __shared__ float red[4][3][32];
    for (int i = tid; i < Hh; i += 128) hs[i] = hsrc[i];
    __syncthreads();

    float ar = 0.f, az = 0.f, an = 0.f;
    int k0 = ks * 64;
    #pragma unroll 8
    for (int k = 0; k < 64; ++k) {
        float hv = hs[k0 + k];
        const float* w = WhT + (k0 + k)*H3;
        ar += w[j]       * hv;
        az += w[Hh + j]  * hv;
        an += w[2*Hh + j]* hv;
    }
    red[ks][0][tj] = ar; red[ks][1][tj] = az; red[ks][2][tj] = an;
    __syncthreads();
    if (ks == 0) {
        ar = red[0][0][tj] + red[1][0][tj] + red[2][0][tj] + red[3][0][tj];
        az = red[0][1][tj] + red[1][1][tj] + red[2][1][tj] + red[3][1][tj];
        an = red[0][2][tj] + red[1][2][tj] + red[2][2][tj] + red[3][2][tj];
        float r = 1.f/(1.f + expf(-(gi[j]        + ar + bh[j])));
        float z = 1.f/(1.f + expf(-(gi[Hh + j]   + az + bh[Hh + j])));
        float n = tanhf(gi[2*Hh + j] + r*(an + bh[2*Hh + j]));
        float hv = (1.f - z)*n + z*hs[j];
        hdst[j] = hv;
        g_encoded[(b*TE + tt)*(2*Hh) + dir*Hh + j] = hv;
    }
}

// ---------------- decoder GRU step ----------------------------------
// grid 256 = b(32) x jc(8); 128 thr = tj(32) x ks(4); unified K=768
__global__ __launch_bounds__(128) void dec_step(const float* __restrict__ bh_d, int t, int pb)
{
    int bx = blockIdx.x;
    int b  = bx & 31;
    int jc = bx >> 5;
    int tid = threadIdx.x;
    int tj = tid & 31, ks = tid >> 5;
    int j = jc*32 + tj;
    const float* csrc = g_ctx[pb] + b*2*Hh;
    const float* hsrc = g_hdec[pb] + b*Hh;
    float*       hdst = g_hdec[pb ^ 1] + b*Hh;
    const float* gi   = g_gi_demb + (b*TD + t)*H3;

    __shared__ float vec[3*Hh];   // 512 ctx + 256 h
    __shared__ float red[4][4][32];
    for (int i = tid; i < 3*Hh; i += 128)
        vec[i] = (i < 2*Hh) ? csrc[i] : hsrc[i - 2*Hh];
    __syncthreads();

    float ar = 0.f, az = 0.f, ain = 0.f, ahn = 0.f;
    int k0 = ks * 192;
    for (int k = k0; k < k0 + 192; ++k) {
        float v = vec[k];
        const float* w = g_WdT + k*H3;
        ar += w[j]      * v;
        az += w[Hh + j] * v;
        float wn = w[2*Hh + j] * v;
        if (k < 2*Hh) ain += wn; else ahn += wn;
    }
    red[ks][0][tj] = ar; red[ks][1][tj] = az; red[ks][2][tj] = ain; red[ks][3][tj] = ahn;
    __syncthreads();
    if (ks == 0) {
        ar  = red[0][0][tj] + red[1][0][tj] + red[2][0][tj] + red[3][0][tj];
        az  = red[0][1][tj] + red[1][1][tj] + red[2][1][tj] + red[3][1][tj];
        ain = red[0][2][tj] + red[1][2][tj] + red[2][2][tj] + red[3][2][tj];
        ahn = red[0][3][tj] + red[1][3][tj] + red[2][3][tj] + red[3][3][tj];
        float r = 1.f/(1.f + expf(-(gi[j]      + ar + bh_d[j])));
        float z = 1.f/(1.f + expf(-(gi[Hh + j] + az + bh_d[Hh + j])));
        float n = tanhf(gi[2*Hh + j] + ain + r*(ahn + bh_d[2*Hh + j]));
        float hv = (1.f - z)*n + z*vec[2*Hh + j];
        hdst[j] = hv;
        g_outs[(b*TD + t)*Hh + j] = hv;
    }
}

// ---------------- attention step (comp, scores, softmax, ctx) --------
// grid 32 (one block per b), 256 threads
__global__ __launch_bounds__(256) void attn_step(const float* __restrict__ W2_b, int t, int pb)
{
    int b = blockIdx.x;
    int tid = threadIdx.x;
    const float* h = g_hdec[pb ^ 1] + b*Hh;
    float* cdst = g_ctx[pb ^ 1] + b*2*Hh;

    __shared__ float sh_h[Hh];
    __shared__ float sh_comp[2*Hh];
    __shared__ float sh_s[TE];
    __shared__ float sred[8];

    if (tid < Hh) sh_h[tid] = h[tid];
    __syncthreads();

    // comp[jj] = h . W2_w[jj,:] + W2_b[jj]   (W2T is [k][512])
    for (int jj = tid; jj < 2*Hh; jj += 256) {
        float c = W2_b[jj];
        for (int k = 0; k < Hh; ++k) c += sh_h[k] * g_W2T[k*2*Hh + jj];
        sh_comp[jj] = c;
    }
    __syncthreads();

    // scores[te] = encoded[b,te,:] . comp  (2 threads per te)
    {
        int te = tid >> 1, half = tid & 1;
        const float* er = g_encoded + (b*TE + te)*2*Hh + half*Hh;
        const float* cp = sh_comp + half*Hh;
        float acc = 0.f;
        for (int k = 0; k < Hh; ++k) acc += er[k]*cp[k];
        acc += __shfl_xor_sync(0xffffffffu, acc, 1);
        if (half == 0) sh_s[te] = acc;
    }
    __syncthreads();

    // softmax over 128
    if (tid < TE) {
        float v = sh_s[tid];
        #pragma unroll
        for (int o = 16; o; o >>= 1) v = fmaxf(v, __shfl_xor_sync(0xffffffffu, v, o));
        if ((tid & 31) == 0) sred[tid >> 5] = v;
    }
    __syncthreads();
    float mx = fmaxf(fmaxf(sred[0], sred[1]), fmaxf(sred[2], sred[3]));
    if (tid < TE) {
        float e = expf(sh_s[tid] - mx);
        sh_s[tid] = e;
        #pragma unroll
        for (int o = 16; o; o >>= 1) e += __shfl_xor_sync(0xffffffffu, e, o);
        if ((tid & 31) == 0) sred[4 + (tid >> 5)] = e;
    }
    __syncthreads();
    float inv = 1.f/(sred[4] + sred[5] + sred[6] + sred[7]);
    if (tid < TE) sh_s[tid] *= inv;
    __syncthreads();

    // ctx[jj] = sum_te p[te] * encoded[b,te,jj]
    for (int jj = tid; jj < 2*Hh; jj += 256) {
        float acc = 0.f;
        const float* e0 = g_encoded + (long)(b*TE)*2*Hh + jj;
        for (int te = 0; te < TE; ++te) acc += sh_s[te]*e0[te*2*Hh];
        cdst[jj] = acc;
    }
}

// ---------------- launch -------------------------------------------
extern "C" void kernel_launch(void* const* d_in, const int* in_sizes, int n_in,
                              void* d_out, int out_size) {
    const int*   enc_in  = (const int*)  d_in[0];
    const int*   dec_in  = (const int*)  d_in[1];
    const float* embed_W = (const float*)d_in[2];
    const float* Wi_f = (const float*)d_in[3];
    const float* Wh_f = (const float*)d_in[4];
    const float* bi_f = (const float*)d_in[5];
    const float* bh_f = (const float*)d_in[6];
    const float* Wi_b = (const float*)d_in[7];
    const float* Wh_b = (const float*)d_in[8];
    const float* bi_b = (const float*)d_in[9];
    const float* bh_b = (const float*)d_in[10];
    const float* Wi_d = (const float*)d_in[11];
    const float* Wh_d = (const float*)d_in[12];
    const float* bi_d = (const float*)d_in[13];
    const float* bh_d = (const float*)d_in[14];
    const float* W1_w = (const float*)d_in[15];
    const float* W1_b = (const float*)d_in[16];
    const float* W2_w = (const float*)d_in[17];
    const float* W2_b = (const float*)d_in[18];
    const float* lin_w = (const float*)d_in[19];
    const float* lin_b = (const float*)d_in[20];

    float *gi_f, *gi_b, *gi_demb, *encoded, *outs, *hdec;
    int *lastidx;
    cudaGetSymbolAddress((void**)&gi_f,    g_gi_f);
    cudaGetSymbolAddress((void**)&gi_b,    g_gi_b);
    cudaGetSymbolAddress((void**)&gi_demb, g_gi_demb);
    cudaGetSymbolAddress((void**)&encoded, g_encoded);
    cudaGetSymbolAddress((void**)&outs,    g_outs);
    cudaGetSymbolAddress((void**)&hdec,    g_hdec);
    cudaGetSymbolAddress((void**)&lastidx, g_lastidx);

    init_kernel<<<1, 256>>>(enc_in);
    transpose_wh<<<(Hh*H3 + 255)/256, 256>>>(Wh_f, 0);
    transpose_wh<<<(Hh*H3 + 255)/256, 256>>>(Wh_b, 1);
    transpose_wd<<<(3*Hh*H3 + 255)/256, 256>>>(Wi_d, Wh_d);
    transpose_w2<<<(Hh*2*Hh + 255)/256, 256>>>(W2_w);

    // encoder / decoder input projections (embedding gather fused)
    sgemm_tn<<<dim3(H3/64, (Bsz*TE + 127)/128), 256>>>(
        embed_W, enc_in, Ee, Wi_f, Ee, 0, bi_f, gi_f, H3, Bsz*TE, H3, Ee);
    sgemm_tn<<<dim3(H3/64, (Bsz*TE + 127)/128), 256>>>(
        embed_W, enc_in, Ee, Wi_b, Ee, 0, bi_b, gi_b, H3, Bsz*TE, H3, Ee);
    sgemm_tn<<<dim3(H3/64, (Bsz*TD + 127)/128), 256>>>(
        embed_W, dec_in, Ee, Wi_d, Ee + 2*Hh, 2*Hh, bi_d, gi_demb, H3, Bsz*TD, H3, Ee);

    // encoder recurrence (both directions per launch)
    for (int s = 0; s < TE; ++s)
        enc_step<<<512, 128>>>(bh_f, bh_b, s, s & 1);

    // h_init = last_states @ W1_w.T + W1_b  (gathered rows of encoded)
    sgemm_tn<<<dim3(Hh/64, 1), 256>>>(
        encoded, lastidx, 2*Hh, W1_w, 2*Hh, 0, W1_b, hdec /* g_hdec[0] */, Hh,
        Bsz, Hh, 2*Hh);

    // decoder with attention
    for (int t = 0; t < TD; ++t) {
        dec_step<<<256, 128>>>(bh_d, t, t & 1);
        attn_step<<<32, 256>>>(W2_b, t, t & 1);
    }

    // logits = outs @ lin_w.T + lin_b
    sgemm_tn<<<dim3(Vv/64, (Bsz*TD + 127)/128), 256>>>(
        outs, nullptr, Hh, lin_w, Hh, 0, lin_b, (float*)d_out, Vv,
        Bsz*TD, Vv, Hh);
}

// round 3
// speedup vs baseline: 2.5780x; 2.5780x over previous
#include <cuda_runtime.h>
#include <math.h>

#define Bsz 32
#define TE  128
#define TD  64
#define Ee  256
#define Hh  256
#define Vv  32000
#define H3  (3*Hh)

// ---------------- device scratch ----------------
__device__ float g_gi_f[Bsz*TE*H3];
__device__ float g_gi_b[Bsz*TE*H3];
__device__ float g_gi_demb[Bsz*TD*H3];
__device__ float g_encoded[Bsz*TE*2*Hh];
__device__ float g_outs[Bsz*TD*Hh];
__device__ float g_henc[2][2][Bsz][Hh];    // [dir][parity][b][j]
__device__ float g_hdec[2][Bsz][Hh];       // [parity][b][j]
__device__ float g_ctxbuf[Bsz][2*Hh];
__device__ float g_M[Bsz*TE*Hh];           // encoded @ W2_w  [4096][256]
__device__ float g_s0[Bsz*TE];             // encoded . W2_b
__device__ float g_W2v[Hh*2*Hh];           // [n=256][j=512] = W2_w^T
__device__ int   g_lastidx[Bsz];
__device__ float g_WhT[2][Hh*H3];          // [k][gate*256 + j]
__device__ float g_WdT[(3*Hh)*H3];         // [k(768)][gate*256 + j]
__device__ unsigned g_bar_enc[8];
__device__ unsigned g_bar_dec;

// ---------------- global barrier ----------------
__device__ __forceinline__ void gbarrier(unsigned* ctr, unsigned target) {
    __syncthreads();
    if (threadIdx.x == 0) {
        __threadfence();
        atomicAdd(ctr, 1u);
        volatile unsigned* p = (volatile unsigned*)ctr;
        while (*p < target) { __nanosleep(32); }
        __threadfence();
    }
    __syncthreads();
}

// ---------------- init ----------------
__global__ void init_kernel(const int* __restrict__ enc_in) {
    int tid = threadIdx.x;
    if (tid < Bsz) {
        int cnt = 0;
        for (int t = 0; t < TE; ++t) cnt += (enc_in[tid*TE + t] > 0) ? 1 : 0;
        int tt = cnt - 1; if (tt < 0) tt += TE;
        g_lastidx[tid] = tid*TE + tt;
    }
    float* he = &g_henc[0][0][0][0];
    for (int i = tid; i < 2*2*Bsz*Hh; i += blockDim.x) he[i] = 0.f;
    float* cx = &g_ctxbuf[0][0];
    for (int i = tid; i < Bsz*2*Hh; i += blockDim.x) cx[i] = 0.f;
    if (tid < 8) g_bar_enc[tid] = 0u;
    if (tid == 0) g_bar_dec = 0u;
}

// ---------------- weight transposes ----------------
__global__ void transpose_wh(const float* __restrict__ Wh, int dir) {
    int idx = blockIdx.x*blockDim.x + threadIdx.x;
    if (idx >= Hh*H3) return;
    int k = idx / H3, jj = idx % H3;
    g_WhT[dir][idx] = Wh[jj*Hh + k];
}
__global__ void transpose_wd(const float* __restrict__ Wi_d, const float* __restrict__ Wh_d) {
    int idx = blockIdx.x*blockDim.x + threadIdx.x;
    if (idx >= 3*Hh*H3) return;
    int k = idx / H3, jj = idx % H3;
    g_WdT[idx] = (k < 2*Hh) ? Wi_d[jj*(Ee + 2*Hh) + k] : Wh_d[jj*Hh + (k - 2*Hh)];
}
__global__ void transpose_w2v(const float* __restrict__ W2_w) {
    int idx = blockIdx.x*blockDim.x + threadIdx.x;   // over 256*512
    if (idx >= Hh*2*Hh) return;
    int n = idx >> 9, j = idx & 511;
    g_W2v[idx] = W2_w[j*Hh + n];
}

// ---------------- s0 = encoded . W2_b ----------------
__global__ void s0_kernel(const float* __restrict__ W2_b) {
    int gw = (blockIdx.x*blockDim.x + threadIdx.x) >> 5;
    int lane = threadIdx.x & 31;
    int nw = (gridDim.x*blockDim.x) >> 5;
    for (int row = gw; row < Bsz*TE; row += nw) {
        const float* e = g_encoded + (long)row*(2*Hh);
        float acc = 0.f;
        for (int i = lane; i < 2*Hh; i += 32) acc += e[i]*W2_b[i];
        #pragma unroll
        for (int o = 16; o; o >>= 1) acc += __shfl_xor_sync(0xffffffffu, acc, o);
        if (lane == 0) g_s0[row] = acc;
    }
}

// ---------------- SGEMM 128x128x16, C = gather(A) @ B^T + bias -------
__global__ __launch_bounds__(256) void sgemm128(
    const float* __restrict__ A, const int* __restrict__ gidx, int lda,
    const float* __restrict__ Bm, int ldb, int boff,
    const float* __restrict__ bias, float* __restrict__ C, int ldc,
    int M, int N, int K)
{
    __shared__ float As[16][132];
    __shared__ float Bs[16][132];
    int tid = threadIdx.x;
    int m0 = blockIdx.y*128, n0 = blockIdx.x*128;
    int ty = tid >> 4, tx = tid & 15;
    int lr = tid >> 2;          // 0..63
    int lk = (tid & 3) * 4;     // 0,4,8,12

    int mA0 = m0 + lr, mA1 = m0 + lr + 64;
    bool vA0 = mA0 < M, vA1 = mA1 < M;
    long rowA0 = 0, rowA1 = 0;
    if (vA0) rowA0 = (long)(gidx ? gidx[mA0] : mA0)*lda;
    if (vA1) rowA1 = (long)(gidx ? gidx[mA1] : mA1)*lda;
    int nB0 = n0 + lr, nB1 = n0 + lr + 64;
    bool vB0 = nB0 < N, vB1 = nB1 < N;
    long rowB0 = (long)nB0*ldb + boff, rowB1 = (long)nB1*ldb + boff;

    const float4 z4 = make_float4(0.f,0.f,0.f,0.f);
    float4 pa0 = vA0 ? *(const float4*)(A + rowA0 + lk) : z4;
    float4 pa1 = vA1 ? *(const float4*)(A + rowA1 + lk) : z4;
    float4 pb0 = vB0 ? *(const float4*)(Bm + rowB0 + lk) : z4;
    float4 pb1 = vB1 ? *(const float4*)(Bm + rowB1 + lk) : z4;

    float acc[8][8];
    #pragma unroll
    for (int i = 0; i < 8; ++i)
        #pragma unroll
        for (int j = 0; j < 8; ++j) acc[i][j] = 0.f;

    int KC = K >> 4;
    for (int kc = 0; kc < KC; ++kc) {
        As[lk+0][lr] = pa0.x; As[lk+1][lr] = pa0.y; As[lk+2][lr] = pa0.z; As[lk+3][lr] = pa0.w;
        As[lk+0][lr+64] = pa1.x; As[lk+1][lr+64] = pa1.y; As[lk+2][lr+64] = pa1.z; As[lk+3][lr+64] = pa1.w;
        Bs[lk+0][lr] = pb0.x; Bs[lk+1][lr] = pb0.y; Bs[lk+2][lr] = pb0.z; Bs[lk+3][lr] = pb0.w;
        Bs[lk+0][lr+64] = pb1.x; Bs[lk+1][lr+64] = pb1.y; Bs[lk+2][lr+64] = pb1.z; Bs[lk+3][lr+64] = pb1.w;
        __syncthreads();
        if (kc + 1 < KC) {
            int ko = (kc+1)*16 + lk;
            pa0 = vA0 ? *(const float4*)(A + rowA0 + ko) : z4;
            pa1 = vA1 ? *(const float4*)(A + rowA1 + ko) : z4;
            pb0 = vB0 ? *(const float4*)(Bm + rowB0 + ko) : z4;
            pb1 = vB1 ? *(const float4*)(Bm + rowB1 + ko) : z4;
        }
        #pragma unroll
        for (int kk = 0; kk < 16; ++kk) {
            float a[8], b[8];
            *(float4*)(a)   = *(const float4*)&As[kk][ty*8];
            *(float4*)(a+4) = *(const float4*)&As[kk][ty*8+4];
            *(float4*)(b)   = *(const float4*)&Bs[kk][tx*8];
            *(float4*)(b+4) = *(const float4*)&Bs[kk][tx*8+4];
            #pragma unroll
            for (int i = 0; i < 8; ++i)
                #pragma unroll
                for (int j = 0; j < 8; ++j) acc[i][j] += a[i]*b[j];
        }
        __syncthreads();
    }
    float bv[8];
    #pragma unroll
    for (int j = 0; j < 8; ++j) {
        int ng = n0 + tx*8 + j;
        bv[j] = (bias && ng < N) ? bias[ng] : 0.f;
    }
    #pragma unroll
    for (int i = 0; i < 8; ++i) {
        int mg = m0 + ty*8 + i;
        if (mg >= M) continue;
        float* Crow = C + (long)mg*ldc + n0 + tx*8;
        if (n0 + 128 <= N) {
            float4 v0, v1;
            v0.x = acc[i][0]+bv[0]; v0.y = acc[i][1]+bv[1]; v0.z = acc[i][2]+bv[2]; v0.w = acc[i][3]+bv[3];
            v1.x = acc[i][4]+bv[4]; v1.y = acc[i][5]+bv[5]; v1.z = acc[i][6]+bv[6]; v1.w = acc[i][7]+bv[7];
            *(float4*)(Crow) = v0; *(float4*)(Crow+4) = v1;
        } else {
            #pragma unroll
            for (int j = 0; j < 8; ++j) {
                int ng = n0 + tx*8 + j;
                if (ng < N) Crow[j] = acc[i][j] + bv[j];
            }
        }
    }
}

// ---------------- persistent encoder ----------------
// 64 blocks: dir(2) x jc(8) x bg(4, 8 batches each). 256 thr = tj(32) x ks(8).
// Dynamic smem: ws[256][96] + hs[8][256] + red[8][8][3][32] + bhs[96]
#define ENC_SMEM_FLOATS (256*96 + 8*256 + 8*8*3*32 + 96)
__global__ __launch_bounds__(256, 1) void enc_persist(
    const float* __restrict__ bh_f, const float* __restrict__ bh_b)
{
    extern __shared__ float sm[];
    float* ws  = sm;
    float* hs  = ws + 256*96;
    float* red = hs + 8*256;
    float* bhs = red + 8*8*3*32;

    int bid = blockIdx.x;
    int dir = bid & 1;
    int jc  = (bid >> 1) & 7;
    int bg  = bid >> 4;
    int grp = dir*4 + bg;
    int tid = threadIdx.x;
    int tj = tid & 31, ks = tid >> 5;
    const float* bh = dir ? bh_b : bh_f;
    const float* WhT = g_WhT[dir];
    const float* gibase = dir ? g_gi_b : g_gi_f;

    for (int idx = tid; idx < 256*96; idx += 256) {
        int k = idx / 96, r = idx - k*96;
        int g = r >> 5, tjj = r & 31;
        ws[idx] = WhT[k*H3 + g*Hh + jc*32 + tjj];
    }
    if (tid < 96) {
        int g = tid >> 5, tjj = tid & 31;
        bhs[tid] = bh[g*Hh + jc*32 + tjj];
    }
    __syncthreads();

    unsigned phase = 0;
    for (int s = 0; s < TE; ++s) {
        int par = s & 1;
        int tt = dir ? (TE-1-s) : s;
        for (int idx = tid; idx < 8*256; idx += 256) {
            int bl = idx >> 8, k = idx & 255;
            hs[idx] = g_henc[dir][par][bg*8 + bl][k];
        }
        int bglob = bg*8 + ks;
        const float* gi = gibase + (long)(bglob*TE + tt)*H3 + jc*32 + tj;
        float gi0 = gi[0], gi1 = gi[Hh], gi2 = gi[2*Hh];
        __syncthreads();

        float a0[8], a1[8], a2[8];
        #pragma unroll
        for (int b = 0; b < 8; ++b) { a0[b]=0.f; a1[b]=0.f; a2[b]=0.f; }
        int kbase = ks*32;
        #pragma unroll 4
        for (int k = 0; k < 32; ++k) {
            const float* w = ws + (kbase+k)*96;
            float w0 = w[tj], w1 = w[32+tj], w2 = w[64+tj];
            #pragma unroll
            for (int b = 0; b < 8; ++b) {
                float hv = hs[b*256 + kbase + k];
                a0[b] += w0*hv; a1[b] += w1*hv; a2[b] += w2*hv;
            }
        }
        #pragma unroll
        for (int b = 0; b < 8; ++b) {
            red[((ks*8+b)*3+0)*32+tj] = a0[b];
            red[((ks*8+b)*3+1)*32+tj] = a1[b];
            red[((ks*8+b)*3+2)*32+tj] = a2[b];
        }
        __syncthreads();
        {
            int b = ks;
            float ar=0.f, az=0.f, an=0.f;
            #pragma unroll
            for (int kk = 0; kk < 8; ++kk) {
                ar += red[((kk*8+b)*3+0)*32+tj];
                az += red[((kk*8+b)*3+1)*32+tj];
                an += red[((kk*8+b)*3+2)*32+tj];
            }
            float r = 1.f/(1.f+expf(-(gi0 + ar + bhs[tj])));
            float z = 1.f/(1.f+expf(-(gi1 + az + bhs[32+tj])));
            float n = tanhf(gi2 + r*(an + bhs[64+tj]));
            float hold = hs[b*256 + jc*32 + tj];
            float hv = (1.f - z)*n + z*hold;
            int bgl = bg*8 + b;
            g_henc[dir][par^1][bgl][jc*32+tj] = hv;
            g_encoded[(long)(bgl*TE+tt)*(2*Hh) + dir*Hh + jc*32 + tj] = hv;
        }
        phase++;
        gbarrier(&g_bar_enc[grp], 8u*phase);
    }
}

// ---------------- persistent decoder ----------------
// 64 blocks: jc(8) x bgrp(8, 4 batches each). 256 thr = tj(32) x ks(8).
__global__ __launch_bounds__(256, 1) void dec_persist(const float* __restrict__ bh_d)
{
    __shared__ float vbuf[4][768];
    __shared__ float red[8][32][16];
    __shared__ float sh_s[TE];
    __shared__ float sred[8];
    __shared__ float sh_h[Hh];

    int bid = blockIdx.x;
    int jc = bid & 7, bgrp = bid >> 3;
    int tid = threadIdx.x;
    int tj = tid & 31, ks = tid >> 5;
    float bh0 = bh_d[jc*32+tj], bh1 = bh_d[Hh+jc*32+tj], bh2 = bh_d[2*Hh+jc*32+tj];

    unsigned phase = 0;
    for (int t = 0; t < TD; ++t) {
        int par = t & 1;
        for (int idx = tid; idx < 4*768; idx += 256) {
            int bl = idx / 768, k = idx - bl*768;
            int b = bgrp*4 + bl;
            vbuf[bl][k] = (k < 512) ? g_ctxbuf[b][k] : g_hdec[par][b][k-512];
        }
        float gi0=0.f, gi1=0.f, gi2=0.f;
        if (tid < 128) {
            int bl = tid >> 5;
            int b = bgrp*4 + bl;
            const float* gi = g_gi_demb + (long)(b*TD+t)*H3 + jc*32 + tj;
            gi0 = gi[0]; gi1 = gi[Hh]; gi2 = gi[2*Hh];
        }
        __syncthreads();

        float ar[4]={0,0,0,0}, az[4]={0,0,0,0}, ain[4]={0,0,0,0}, ahn[4]={0,0,0,0};
        int k0 = ks*96;
        #pragma unroll 4
        for (int kk = 0; kk < 96; ++kk) {
            int k = k0 + kk;
            const float* w = g_WdT + (long)k*H3 + jc*32 + tj;
            float w0 = w[0], w1 = w[Hh], w2 = w[2*Hh];
            bool isCtx = (k < 512);
            #pragma unroll
            for (int bl = 0; bl < 4; ++bl) {
                float v = vbuf[bl][k];
                ar[bl] += w0*v; az[bl] += w1*v;
                if (isCtx) ain[bl] += w2*v; else ahn[bl] += w2*v;
            }
        }
        #pragma unroll
        for (int bl = 0; bl < 4; ++bl) {
            red[ks][tj][bl*4+0] = ar[bl];
            red[ks][tj][bl*4+1] = az[bl];
            red[ks][tj][bl*4+2] = ain[bl];
            red[ks][tj][bl*4+3] = ahn[bl];
        }
        __syncthreads();
        if (tid < 128) {
            int bl = tid >> 5;
            float sar=0.f, saz=0.f, sin_=0.f, shn=0.f;
            #pragma unroll
            for (int kk = 0; kk < 8; ++kk) {
                sar  += red[kk][tj][bl*4+0];
                saz  += red[kk][tj][bl*4+1];
                sin_ += red[kk][tj][bl*4+2];
                shn  += red[kk][tj][bl*4+3];
            }
            float r = 1.f/(1.f+expf(-(gi0 + sar + bh0)));
            float z = 1.f/(1.f+expf(-(gi1 + saz + bh1)));
            float n = tanhf(gi2 + sin_ + r*(shn + bh2));
            int b = bgrp*4 + bl;
            float hold = vbuf[bl][512 + jc*32 + tj];
            float hv = (1.f-z)*n + z*hold;
            g_hdec[par^1][b][jc*32+tj] = hv;
            g_outs[(long)(b*TD+t)*Hh + jc*32 + tj] = hv;
        }
        phase++;
        gbarrier(&g_bar_dec, 64u*phase);

        if (bid < 32) {
            int b = bid;
            sh_h[tid] = g_hdec[par^1][b][tid & 255];
            __syncthreads();
            int wid = tid >> 5, lane = tid & 31;
            float4 h0 = *(const float4*)&sh_h[lane*8];
            float4 h1 = *(const float4*)&sh_h[lane*8+4];
            for (int i = 0; i < 16; ++i) {
                int te = wid*16 + i;
                const float* Mr = g_M + (long)(b*TE+te)*Hh + lane*8;
                float4 m0 = *(const float4*)(Mr);
                float4 m1 = *(const float4*)(Mr+4);
                float acc = m0.x*h0.x + m0.y*h0.y + m0.z*h0.z + m0.w*h0.w
                          + m1.x*h1.x + m1.y*h1.y + m1.z*h1.z + m1.w*h1.w;
                #pragma unroll
                for (int o = 16; o; o >>= 1) acc += __shfl_xor_sync(0xffffffffu, acc, o);
                if (lane == 0) sh_s[te] = acc + g_s0[b*TE+te];
            }
            __syncthreads();
            if (tid < TE) {
                float v = sh_s[tid];
                #pragma unroll
                for (int o = 16; o; o >>= 1) v = fmaxf(v, __shfl_xor_sync(0xffffffffu, v, o));
                if ((tid & 31) == 0) sred[tid >> 5] = v;
            }
            __syncthreads();
            float mx = fmaxf(fmaxf(sred[0], sred[1]), fmaxf(sred[2], sred[3]));
            if (tid < TE) {
                float e = expf(sh_s[tid] - mx);
                sh_s[tid] = e;
                #pragma unroll
                for (int o = 16; o; o >>= 1) e += __shfl_xor_sync(0xffffffffu, e, o);
                if ((tid & 31) == 0) sred[4 + (tid >> 5)] = e;
            }
            __syncthreads();
            float inv = 1.f/(sred[4] + sred[5] + sred[6] + sred[7]);
            if (tid < TE) sh_s[tid] *= inv;
            __syncthreads();
            for (int jj = tid; jj < 2*Hh; jj += 256) {
                float acc = 0.f;
                const float* e0 = g_encoded + (long)(b*TE)*(2*Hh) + jj;
                #pragma unroll 8
                for (int te = 0; te < TE; ++te) acc += sh_s[te]*e0[te*(2*Hh)];
                g_ctxbuf[b][jj] = acc;
            }
        }
        phase++;
        gbarrier(&g_bar_dec, 64u*phase);
    }
}

// ---------------- launch ----------------
extern "C" void kernel_launch(void* const* d_in, const int* in_sizes, int n_in,
                              void* d_out, int out_size) {
    const int*   enc_in  = (const int*)  d_in[0];
    const int*   dec_in  = (const int*)  d_in[1];
    const float* embed_W = (const float*)d_in[2];
    const float* Wi_f = (const float*)d_in[3];
    const float* Wh_f = (const float*)d_in[4];
    const float* bi_f = (const float*)d_in[5];
    const float* bh_f = (const float*)d_in[6];
    const float* Wi_b = (const float*)d_in[7];
    const float* Wh_b = (const float*)d_in[8];
    const float* bi_b = (const float*)d_in[9];
    const float* bh_b = (const float*)d_in[10];
    const float* Wi_d = (const float*)d_in[11];
    const float* Wh_d = (const float*)d_in[12];
    const float* bi_d = (const float*)d_in[13];
    const float* bh_d = (const float*)d_in[14];
    const float* W1_w = (const float*)d_in[15];
    const float* W1_b = (const float*)d_in[16];
    const float* W2_w = (const float*)d_in[17];
    const float* W2_b = (const float*)d_in[18];
    const float* lin_w = (const float*)d_in[19];
    const float* lin_b = (const float*)d_in[20];

    float *gi_f, *gi_b, *gi_demb, *encoded, *outs, *hdec, *w2v, *Mp;
    int *lastidx;
    cudaGetSymbolAddress((void**)&gi_f,    g_gi_f);
    cudaGetSymbolAddress((void**)&gi_b,    g_gi_b);
    cudaGetSymbolAddress((void**)&gi_demb, g_gi_demb);
    cudaGetSymbolAddress((void**)&encoded, g_encoded);
    cudaGetSymbolAddress((void**)&outs,    g_outs);
    cudaGetSymbolAddress((void**)&hdec,    g_hdec);
    cudaGetSymbolAddress((void**)&w2v,     g_W2v);
    cudaGetSymbolAddress((void**)&Mp,      g_M);
    cudaGetSymbolAddress((void**)&lastidx, g_lastidx);

    static int smem_set = 0;
    if (!smem_set) {
        cudaFuncSetAttribute(enc_persist, cudaFuncAttributeMaxDynamicSharedMemorySize,
                             ENC_SMEM_FLOATS*sizeof(float));
        smem_set = 1;
    }

    init_kernel<<<1, 256>>>(enc_in);
    transpose_wh<<<(Hh*H3 + 255)/256, 256>>>(Wh_f, 0);
    transpose_wh<<<(Hh*H3 + 255)/256, 256>>>(Wh_b, 1);
    transpose_wd<<<(3*Hh*H3 + 255)/256, 256>>>(Wi_d, Wh_d);
    transpose_w2v<<<(Hh*2*Hh + 255)/256, 256>>>(W2_w);

    // input projections (embedding gather fused): gi = emb @ Wi^T + bi
    sgemm128<<<dim3(H3/128, Bsz*TE/128), 256>>>(
        embed_W, enc_in, Ee, Wi_f, Ee, 0, bi_f, gi_f, H3, Bsz*TE, H3, Ee);
    sgemm128<<<dim3(H3/128, Bsz*TE/128), 256>>>(
        embed_W, enc_in, Ee, Wi_b, Ee, 0, bi_b, gi_b, H3, Bsz*TE, H3, Ee);
    sgemm128<<<dim3(H3/128, Bsz*TD/128), 256>>>(
        embed_W, dec_in, Ee, Wi_d, Ee + 2*Hh, 2*Hh, bi_d, gi_demb, H3, Bsz*TD, H3, Ee);

    // encoder recurrence (persistent, 128 steps internally)
    enc_persist<<<64, 256, ENC_SMEM_FLOATS*sizeof(float)>>>(bh_f, bh_b);

    // attention precompute: M = encoded @ W2_w  (via W2v = W2_w^T), s0 = encoded . W2_b
    sgemm128<<<dim3(Hh/128, Bsz*TE/128), 256>>>(
        encoded, nullptr, 2*Hh, w2v, 2*Hh, 0, nullptr, Mp, Hh, Bsz*TE, Hh, 2*Hh);
    s0_kernel<<<64, 256>>>(W2_b);

    // h_init = last_states @ W1_w^T + W1_b  -> g_hdec[0]
    sgemm128<<<dim3(2, 1), 256>>>(
        encoded, lastidx, 2*Hh, W1_w, 2*Hh, 0, W1_b, hdec, Hh, Bsz, Hh, 2*Hh);

    // decoder + attention (persistent, 64 steps internally)
    dec_persist<<<64, 256>>>(bh_d);

    // logits = outs @ lin_w^T + lin_b
    sgemm128<<<dim3(Vv/128, Bsz*TD/128), 256>>>(
        outs, nullptr, Hh, lin_w, Hh, 0, lin_b, (float*)d_out, Vv,
        Bsz*TD, Vv, Hh);
}

// round 7
// speedup vs baseline: 3.0583x; 1.1863x over previous
#include <cuda_runtime.h>
#include <cuda_bf16.h>
#include <math.h>
#include <stdint.h>

#define Bsz 32
#define TE  128
#define TD  64
#define Ee  256
#define Hh  256
#define Vv  32000
#define H3  (3*Hh)

// ---------------- device scratch ----------------
__device__ float g_gi_f[Bsz*TE*H3];
__device__ float g_gi_b[Bsz*TE*H3];
__device__ float g_gi_demb[Bsz*TD*H3];
__device__ float g_encoded[Bsz*TE*2*Hh];
__device__ float g_outs[Bsz*TD*Hh];
__device__ float g_henc[2][2][Bsz][Hh];
__device__ float g_hdec[2][Bsz][Hh];
__device__ float g_ctxbuf[Bsz][2*Hh];
__device__ float g_M[Bsz*TE*Hh];
__device__ float g_s0[Bsz*TE];
__device__ float g_W2v[Hh*2*Hh];
__device__ int   g_lastidx[Bsz];
__device__ float g_WhT[2][Hh*H3];
__device__ float g_WdT[(3*Hh)*H3];
__device__ unsigned g_bar_enc[8];
__device__ unsigned g_bar_dec;
// three-term split-bf16 operands: [rows][768]
// A (outs): [a_hi | a_lo | a_hi] ; B (lin_w): [b_hi | b_hi | b_lo]
__device__ __nv_bfloat16 g_linw3[(long)Vv*768];
__device__ __nv_bfloat16 g_outs3[(long)Bsz*TD*768];

// ---------------- helpers ----------------
__device__ __forceinline__ uint32_t smem_u32(const void* p) {
    uint32_t a;
    asm("{ .reg .u64 t; cvta.to.shared.u64 t, %1; cvt.u32.u64 %0, t; }" : "=r"(a) : "l"(p));
    return a;
}

__device__ __forceinline__ void gbarrier(unsigned* ctr, unsigned target) {
    __syncthreads();
    if (threadIdx.x == 0) {
        __threadfence();
        atomicAdd(ctr, 1u);
        volatile unsigned* p = (volatile unsigned*)ctr;
        while (*p < target) { __nanosleep(32); }
        __threadfence();
    }
    __syncthreads();
}

// ---------------- init ----------------
__global__ void init_kernel(const int* __restrict__ enc_in) {
    int tid = threadIdx.x;
    if (tid < Bsz) {
        int cnt = 0;
        for (int t = 0; t < TE; ++t) cnt += (enc_in[tid*TE + t] > 0) ? 1 : 0;
        int tt = cnt - 1; if (tt < 0) tt += TE;
        g_lastidx[tid] = tid*TE + tt;
    }
    float* he = &g_henc[0][0][0][0];
    for (int i = tid; i < 2*2*Bsz*Hh; i += blockDim.x) he[i] = 0.f;
    float* cx = &g_ctxbuf[0][0];
    for (int i = tid; i < Bsz*2*Hh; i += blockDim.x) cx[i] = 0.f;
    if (tid < 8) g_bar_enc[tid] = 0u;
    if (tid == 0) g_bar_dec = 0u;
}

// ---------------- fused weight transposes ----------------
__global__ void transpose_all(
    const float* __restrict__ Wh_f, const float* __restrict__ Wh_b,
    const float* __restrict__ Wi_d, const float* __restrict__ Wh_d,
    const float* __restrict__ W2_w)
{
    int idx = blockIdx.x*blockDim.x + threadIdx.x;
    if (idx < 196608) {
        int k = idx / H3, jj = idx % H3;
        g_WhT[0][idx] = Wh_f[jj*Hh + k];
    } else if (idx < 393216) {
        int i = idx - 196608;
        int k = i / H3, jj = i % H3;
        g_WhT[1][i] = Wh_b[jj*Hh + k];
    } else if (idx < 983040) {
        int i = idx - 393216;
        int k = i / H3, jj = i % H3;
        g_WdT[i] = (k < 2*Hh) ? Wi_d[jj*(Ee + 2*Hh) + k] : Wh_d[jj*Hh + (k - 2*Hh)];
    } else if (idx < 1114112) {
        int i = idx - 983040;
        int n = i >> 9, j = i & 511;
        g_W2v[i] = W2_w[j*Hh + n];
    }
}

// ---------------- split fp32 row[256] -> bf16 row[768] ---------------
// pattern 0 (A/outs):  [hi | lo | hi]
// pattern 1 (B/lin_w): [hi | hi | lo]
__global__ void convert_split3(const float* __restrict__ src, __nv_bfloat16* __restrict__ dst,
                               int total, int pattern) {
    int idx = blockIdx.x*blockDim.x + threadIdx.x;
    if (idx >= total) return;
    int r = idx >> 8, k = idx & 255;
    float v = src[idx];
    __nv_bfloat16 hi = __float2bfloat16(v);
    __nv_bfloat16 lo = __float2bfloat16(v - __bfloat162float(hi));
    long base = (long)r*768 + k;
    if (pattern == 0) {
        dst[base]       = hi;
        dst[base + 256] = lo;
        dst[base + 512] = hi;
    } else {
        dst[base]       = hi;
        dst[base + 256] = hi;
        dst[base + 512] = lo;
    }
}

// ---------------- s0 = encoded . W2_b ----------------
__global__ void s0_kernel(const float* __restrict__ W2_b) {
    int gw = (blockIdx.x*blockDim.x + threadIdx.x) >> 5;
    int lane = threadIdx.x & 31;
    int nw = (gridDim.x*blockDim.x) >> 5;
    for (int row = gw; row < Bsz*TE; row += nw) {
        const float* e = g_encoded + (long)row*(2*Hh);
        float acc = 0.f;
        for (int i = lane; i < 2*Hh; i += 32) acc += e[i]*W2_b[i];
        #pragma unroll
        for (int o = 16; o; o >>= 1) acc += __shfl_xor_sync(0xffffffffu, acc, o);
        if (lane == 0) g_s0[row] = acc;
    }
}

// ---------------- SGEMM 128x128x16, C = gather(A) @ B^T + bias -------
__global__ __launch_bounds__(256) void sgemm128(
    const float* __restrict__ A, const int* __restrict__ gidx, int lda,
    const float* __restrict__ Bm, int ldb, int boff,
    const float* __restrict__ bias, float* __restrict__ C, int ldc,
    int M, int N, int K)
{
    __shared__ float As[16][132];
    __shared__ float Bs[16][132];
    int tid = threadIdx.x;
    int m0 = blockIdx.y*128, n0 = blockIdx.x*128;
    int ty = tid >> 4, tx = tid & 15;
    int lr = tid >> 2;
    int lk = (tid & 3) * 4;

    int mA0 = m0 + lr, mA1 = m0 + lr + 64;
    bool vA0 = mA0 < M, vA1 = mA1 < M;
    long rowA0 = 0, rowA1 = 0;
    if (vA0) rowA0 = (long)(gidx ? gidx[mA0] : mA0)*lda;
    if (vA1) rowA1 = (long)(gidx ? gidx[mA1] : mA1)*lda;
    int nB0 = n0 + lr, nB1 = n0 + lr + 64;
    bool vB0 = nB0 < N, vB1 = nB1 < N;
    long rowB0 = (long)nB0*ldb + boff, rowB1 = (long)nB1*ldb + boff;

    const float4 z4 = make_float4(0.f,0.f,0.f,0.f);
    float4 pa0 = vA0 ? *(const float4*)(A + rowA0 + lk) : z4;
    float4 pa1 = vA1 ? *(const float4*)(A + rowA1 + lk) : z4;
    float4 pb0 = vB0 ? *(const float4*)(Bm + rowB0 + lk) : z4;
    float4 pb1 = vB1 ? *(const float4*)(Bm + rowB1 + lk) : z4;

    float acc[8][8];
    #pragma unroll
    for (int i = 0; i < 8; ++i)
        #pragma unroll
        for (int j = 0; j < 8; ++j) acc[i][j] = 0.f;

    int KC = K >> 4;
    for (int kc = 0; kc < KC; ++kc) {
        As[lk+0][lr] = pa0.x; As[lk+1][lr] = pa0.y; As[lk+2][lr] = pa0.z; As[lk+3][lr] = pa0.w;
        As[lk+0][lr+64] = pa1.x; As[lk+1][lr+64] = pa1.y; As[lk+2][lr+64] = pa1.z; As[lk+3][lr+64] = pa1.w;
        Bs[lk+0][lr] = pb0.x; Bs[lk+1][lr] = pb0.y; Bs[lk+2][lr] = pb0.z; Bs[lk+3][lr] = pb0.w;
        Bs[lk+0][lr+64] = pb1.x; Bs[lk+1][lr+64] = pb1.y; Bs[lk+2][lr+64] = pb1.z; Bs[lk+3][lr+64] = pb1.w;
        __syncthreads();
        if (kc + 1 < KC) {
            int ko = (kc+1)*16 + lk;
            pa0 = vA0 ? *(const float4*)(A + rowA0 + ko) : z4;
            pa1 = vA1 ? *(const float4*)(A + rowA1 + ko) : z4;
            pb0 = vB0 ? *(const float4*)(Bm + rowB0 + ko) : z4;
            pb1 = vB1 ? *(const float4*)(Bm + rowB1 + ko) : z4;
        }
        #pragma unroll
        for (int kk = 0; kk < 16; ++kk) {
            float a[8], b[8];
            *(float4*)(a)   = *(const float4*)&As[kk][ty*8];
            *(float4*)(a+4) = *(const float4*)&As[kk][ty*8+4];
            *(float4*)(b)   = *(const float4*)&Bs[kk][tx*8];
            *(float4*)(b+4) = *(const float4*)&Bs[kk][tx*8+4];
            #pragma unroll
            for (int i = 0; i < 8; ++i)
                #pragma unroll
                for (int j = 0; j < 8; ++j) acc[i][j] += a[i]*b[j];
        }
        __syncthreads();
    }
    float bv[8];
    #pragma unroll
    for (int j = 0; j < 8; ++j) {
        int ng = n0 + tx*8 + j;
        bv[j] = (bias && ng < N) ? bias[ng] : 0.f;
    }
    #pragma unroll
    for (int i = 0; i < 8; ++i) {
        int mg = m0 + ty*8 + i;
        if (mg >= M) continue;
        float* Crow = C + (long)mg*ldc + n0 + tx*8;
        if (n0 + 128 <= N) {
            float4 v0, v1;
            v0.x = acc[i][0]+bv[0]; v0.y = acc[i][1]+bv[1]; v0.z = acc[i][2]+bv[2]; v0.w = acc[i][3]+bv[3];
            v1.x = acc[i][4]+bv[4]; v1.y = acc[i][5]+bv[5]; v1.z = acc[i][6]+bv[6]; v1.w = acc[i][7]+bv[7];
            *(float4*)(Crow) = v0; *(float4*)(Crow+4) = v1;
        } else {
            #pragma unroll
            for (int j = 0; j < 8; ++j) {
                int ng = n0 + tx*8 + j;
                if (ng < N) Crow[j] = acc[i][j] + bv[j];
            }
        }
    }
}

// ---------------- HMMA bf16 classifier GEMM --------------------------
// C[2048][32000] = A3[2048][768] @ B3[32000][768]^T + bias, fp32 accum.
// Three-term split along K: hi*hi + lo*hi + hi*lo.
// Tile 128x128, BK=64, 12 K-chunks. 8 warps = 4(M) x 2(N), warp = 32x64.
__global__ __launch_bounds__(256) void cls_hmma(
    const __nv_bfloat16* __restrict__ A3,
    const __nv_bfloat16* __restrict__ B3,
    const float* __restrict__ bias,
    float* __restrict__ C)
{
    __shared__ __nv_bfloat16 As[128][72];
    __shared__ __nv_bfloat16 Bs[128][72];
    int tid = threadIdx.x;
    int wid = tid >> 5, lane = tid & 31;
    int m0 = blockIdx.y*128, n0 = blockIdx.x*128;
    int wm = (wid & 3)*32, wn = (wid >> 2)*64;

    float acc[2][8][4];
    #pragma unroll
    for (int i = 0; i < 2; ++i)
        #pragma unroll
        for (int j = 0; j < 8; ++j)
            #pragma unroll
            for (int k = 0; k < 4; ++k) acc[i][j][k] = 0.f;

    const uint4* Ag = (const uint4*)(A3 + (long)m0*768);
    const uint4* Bg = (const uint4*)(B3 + (long)n0*768);
    int lr = tid >> 3;            // 0..31
    int lc = (tid & 7);           // uint4 index within 64-col chunk

    int a_row = lane & 15, a_koff = (lane >> 4)*8;
    int b_row = lane & 7, b_koff = ((lane >> 3) & 1)*8;

    for (int kc = 0; kc < 12; ++kc) {
        int kb8 = kc*8;           // uint4 offset of this K chunk (row stride 96 uint4)
        #pragma unroll
        for (int i = 0; i < 4; ++i) {
            int r = lr + i*32;
            *(uint4*)&As[r][lc*8] = Ag[(long)r*96 + kb8 + lc];
            *(uint4*)&Bs[r][lc*8] = Bg[(long)r*96 + kb8 + lc];
        }
        __syncthreads();
        #pragma unroll
        for (int ks = 0; ks < 4; ++ks) {
            int k16 = ks*16;
            uint32_t a[2][4];
            #pragma unroll
            for (int im = 0; im < 2; ++im) {
                uint32_t addr = smem_u32(&As[wm + im*16 + a_row][k16 + a_koff]);
                asm volatile("ldmatrix.sync.aligned.m8n8.x4.shared.b16 {%0,%1,%2,%3}, [%4];"
                    : "=r"(a[im][0]), "=r"(a[im][1]), "=r"(a[im][2]), "=r"(a[im][3])
                    : "r"(addr));
            }
            #pragma unroll
            for (int in = 0; in < 8; ++in) {
                uint32_t b0, b1;
                uint32_t addr = smem_u32(&Bs[wn + in*8 + b_row][k16 + b_koff]);
                asm volatile("ldmatrix.sync.aligned.m8n8.x2.shared.b16 {%0,%1}, [%2];"
                    : "=r"(b0), "=r"(b1) : "r"(addr));
                #pragma unroll
                for (int im = 0; im < 2; ++im) {
                    asm volatile(
                        "mma.sync.aligned.m16n8k16.row.col.f32.bf16.bf16.f32 "
                        "{%0,%1,%2,%3}, {%4,%5,%6,%7}, {%8,%9}, {%0,%1,%2,%3};"
                        : "+f"(acc[im][in][0]), "+f"(acc[im][in][1]),
                          "+f"(acc[im][in][2]), "+f"(acc[im][in][3])
                        : "r"(a[im][0]), "r"(a[im][1]), "r"(a[im][2]), "r"(a[im][3]),
                          "r"(b0), "r"(b1));
                }
            }
        }
        __syncthreads();
    }

    int gr = lane >> 2, gc = (lane & 3)*2;
    #pragma unroll
    for (int im = 0; im < 2; ++im) {
        #pragma unroll
        for (int in = 0; in < 8; ++in) {
            int m = m0 + wm + im*16 + gr;
            int n = n0 + wn + in*8 + gc;
            float b0 = bias[n], b1 = bias[n+1];
            float2 v0 = make_float2(acc[im][in][0] + b0, acc[im][in][1] + b1);
            float2 v1 = make_float2(acc[im][in][2] + b0, acc[im][in][3] + b1);
            *(float2*)(C + (long)m*Vv + n)     = v0;
            *(float2*)(C + (long)(m+8)*Vv + n) = v1;
        }
    }
}

// ---------------- persistent encoder ----------------
#define ENC_SMEM_FLOATS (256*96 + 8*256 + 8*8*3*32 + 96)
__global__ __launch_bounds__(256, 1) void enc_persist(
    const float* __restrict__ bh_f, const float* __restrict__ bh_b)
{
    extern __shared__ float sm[];
    float* ws  = sm;
    float* hs  = ws + 256*96;
    float* red = hs + 8*256;
    float* bhs = red + 8*8*3*32;

    int bid = blockIdx.x;
    int dir = bid & 1;
    int jc  = (bid >> 1) & 7;
    int bg  = bid >> 4;
    int grp = dir*4 + bg;
    int tid = threadIdx.x;
    int tj = tid & 31, ks = tid >> 5;
    const float* bh = dir ? bh_b : bh_f;
    const float* WhT = g_WhT[dir];
    const float* gibase = dir ? g_gi_b : g_gi_f;

    for (int idx = tid; idx < 256*96; idx += 256) {
        int k = idx / 96, r = idx - k*96;
        int g = r >> 5, tjj = r & 31;
        ws[idx] = WhT[k*H3 + g*Hh + jc*32 + tjj];
    }
    if (tid < 96) {
        int g = tid >> 5, tjj = tid & 31;
        bhs[tid] = bh[g*Hh + jc*32 + tjj];
    }
    __syncthreads();

    unsigned phase = 0;
    for (int s = 0; s < TE; ++s) {
        int par = s & 1;
        int tt = dir ? (TE-1-s) : s;
        for (int idx = tid; idx < 8*256; idx += 256) {
            int bl = idx >> 8, k = idx & 255;
            hs[idx] = g_henc[dir][par][bg*8 + bl][k];
        }
        int bglob = bg*8 + ks;
        const float* gi = gibase + (long)(bglob*TE + tt)*H3 + jc*32 + tj;
        float gi0 = gi[0], gi1 = gi[Hh], gi2 = gi[2*Hh];
        __syncthreads();

        float a0[8], a1[8], a2[8];
        #pragma unroll
        for (int b = 0; b < 8; ++b) { a0[b]=0.f; a1[b]=0.f; a2[b]=0.f; }
        int kbase = ks*32;
        #pragma unroll 4
        for (int k = 0; k < 32; ++k) {
            const float* w = ws + (kbase+k)*96;
            float w0 = w[tj], w1 = w[32+tj], w2 = w[64+tj];
            #pragma unroll
            for (int b = 0; b < 8; ++b) {
                float hv = hs[b*256 + kbase + k];
                a0[b] += w0*hv; a1[b] += w1*hv; a2[b] += w2*hv;
            }
        }
        #pragma unroll
        for (int b = 0; b < 8; ++b) {
            red[((ks*8+b)*3+0)*32+tj] = a0[b];
            red[((ks*8+b)*3+1)*32+tj] = a1[b];
            red[((ks*8+b)*3+2)*32+tj] = a2[b];
        }
        __syncthreads();
        {
            int b = ks;
            float ar=0.f, az=0.f, an=0.f;
            #pragma unroll
            for (int kk = 0; kk < 8; ++kk) {
                ar += red[((kk*8+b)*3+0)*32+tj];
                az += red[((kk*8+b)*3+1)*32+tj];
                an += red[((kk*8+b)*3+2)*32+tj];
            }
            float r = 1.f/(1.f+expf(-(gi0 + ar + bhs[tj])));
            float z = 1.f/(1.f+expf(-(gi1 + az + bhs[32+tj])));
            float n = tanhf(gi2 + r*(an + bhs[64+tj]));
            float hold = hs[b*256 + jc*32 + tj];
            float hv = (1.f - z)*n + z*hold;
            int bgl = bg*8 + b;
            g_henc[dir][par^1][bgl][jc*32+tj] = hv;
            g_encoded[(long)(bgl*TE+tt)*(2*Hh) + dir*Hh + jc*32 + tj] = hv;
        }
        phase++;
        gbarrier(&g_bar_enc[grp], 8u*phase);
    }
}

// ---------------- persistent decoder ----------------
__global__ __launch_bounds__(256, 1) void dec_persist(const float* __restrict__ bh_d)
{
    __shared__ float vbuf[4][768];
    __shared__ float red[8][32][16];
    __shared__ float sh_s[TE];
    __shared__ float sred[8];
    __shared__ float sh_h[Hh];

    int bid = blockIdx.x;
    int jc = bid & 7, bgrp = bid >> 3;
    int tid = threadIdx.x;
    int tj = tid & 31, ks = tid >> 5;
    float bh0 = bh_d[jc*32+tj], bh1 = bh_d[Hh+jc*32+tj], bh2 = bh_d[2*Hh+jc*32+tj];

    unsigned phase = 0;
    for (int t = 0; t < TD; ++t) {
        int par = t & 1;
        for (int idx = tid; idx < 4*768; idx += 256) {
            int bl = idx / 768, k = idx - bl*768;
            int b = bgrp*4 + bl;
            vbuf[bl][k] = (k < 512) ? g_ctxbuf[b][k] : g_hdec[par][b][k-512];
        }
        float gi0=0.f, gi1=0.f, gi2=0.f;
        if (tid < 128) {
            int bl = tid >> 5;
            int b = bgrp*4 + bl;
            const float* gi = g_gi_demb + (long)(b*TD+t)*H3 + jc*32 + tj;
            gi0 = gi[0]; gi1 = gi[Hh]; gi2 = gi[2*Hh];
        }
        __syncthreads();

        float ar[4]={0,0,0,0}, az[4]={0,0,0,0}, ain[4]={0,0,0,0}, ahn[4]={0,0,0,0};
        int k0 = ks*96;
        #pragma unroll 4
        for (int kk = 0; kk < 96; ++kk) {
            int k = k0 + kk;
            const float* w = g_WdT + (long)k*H3 + jc*32 + tj;
            float w0 = w[0], w1 = w[Hh], w2 = w[2*Hh];
            bool isCtx = (k < 512);
            #pragma unroll
            for (int bl = 0; bl < 4; ++bl) {
                float v = vbuf[bl][k];
                ar[bl] += w0*v; az[bl] += w1*v;
                if (isCtx) ain[bl] += w2*v; else ahn[bl] += w2*v;
            }
        }
        #pragma unroll
        for (int bl = 0; bl < 4; ++bl) {
            red[ks][tj][bl*4+0] = ar[bl];
            red[ks][tj][bl*4+1] = az[bl];
            red[ks][tj][bl*4+2] = ain[bl];
            red[ks][tj][bl*4+3] = ahn[bl];
        }
        __syncthreads();
        if (tid < 128) {
            int bl = tid >> 5;
            float sar=0.f, saz=0.f, sin_=0.f, shn=0.f;
            #pragma unroll
            for (int kk = 0; kk < 8; ++kk) {
                sar  += red[kk][tj][bl*4+0];
                saz  += red[kk][tj][bl*4+1];
                sin_ += red[kk][tj][bl*4+2];
                shn  += red[kk][tj][bl*4+3];
            }
            float r = 1.f/(1.f+expf(-(gi0 + sar + bh0)));
            float z = 1.f/(1.f+expf(-(gi1 + saz + bh1)));
            float n = tanhf(gi2 + sin_ + r*(shn + bh2));
            int b = bgrp*4 + bl;
            float hold = vbuf[bl][512 + jc*32 + tj];
            float hv = (1.f-z)*n + z*hold;
            g_hdec[par^1][b][jc*32+tj] = hv;
            g_outs[(long)(b*TD+t)*Hh + jc*32 + tj] = hv;
        }
        phase++;
        gbarrier(&g_bar_dec, 64u*phase);

        if (bid < 32) {
            int b = bid;
            sh_h[tid] = g_hdec[par^1][b][tid & 255];
            __syncthreads();
            int wid = tid >> 5, lane = tid & 31;
            float4 h0 = *(const float4*)&sh_h[lane*8];
            float4 h1 = *(const float4*)&sh_h[lane*8+4];
            for (int i = 0; i < 16; ++i) {
                int te = wid*16 + i;
                const float* Mr = g_M + (long)(b*TE+te)*Hh + lane*8;
                float4 m0 = *(const float4*)(Mr);
                float4 m1 = *(const float4*)(Mr+4);
                float acc = m0.x*h0.x + m0.y*h0.y + m0.z*h0.z + m0.w*h0.w
                          + m1.x*h1.x + m1.y*h1.y + m1.z*h1.z + m1.w*h1.w;
                #pragma unroll
                for (int o = 16; o; o >>= 1) acc += __shfl_xor_sync(0xffffffffu, acc, o);
                if (lane == 0) sh_s[te] = acc + g_s0[b*TE+te];
            }
            __syncthreads();
            if (tid < TE) {
                float v = sh_s[tid];
                #pragma unroll
                for (int o = 16; o; o >>= 1) v = fmaxf(v, __shfl_xor_sync(0xffffffffu, v, o));
                if ((tid & 31) == 0) sred[tid >> 5] = v;
            }
            __syncthreads();
            float mx = fmaxf(fmaxf(sred[0], sred[1]), fmaxf(sred[2], sred[3]));
            if (tid < TE) {
                float e = expf(sh_s[tid] - mx);
                sh_s[tid] = e;
                #pragma unroll
                for (int o = 16; o; o >>= 1) e += __shfl_xor_sync(0xffffffffu, e, o);
                if ((tid & 31) == 0) sred[4 + (tid >> 5)] = e;
            }
            __syncthreads();
            float inv = 1.f/(sred[4] + sred[5] + sred[6] + sred[7]);
            if (tid < TE) sh_s[tid] *= inv;
            __syncthreads();
            for (int jj = tid; jj < 2*Hh; jj += 256) {
                float acc = 0.f;
                const float* e0 = g_encoded + (long)(b*TE)*(2*Hh) + jj;
                #pragma unroll 8
                for (int te = 0; te < TE; ++te) acc += sh_s[te]*e0[te*(2*Hh)];
                g_ctxbuf[b][jj] = acc;
            }
        }
        phase++;
        gbarrier(&g_bar_dec, 64u*phase);
    }
}

// ---------------- launch ----------------
extern "C" void kernel_launch(void* const* d_in, const int* in_sizes, int n_in,
                              void* d_out, int out_size) {
    const int*   enc_in  = (const int*)  d_in[0];
    const int*   dec_in  = (const int*)  d_in[1];
    const float* embed_W = (const float*)d_in[2];
    const float* Wi_f = (const float*)d_in[3];
    const float* Wh_f = (const float*)d_in[4];
    const float* bi_f = (const float*)d_in[5];
    const float* bh_f = (const float*)d_in[6];
    const float* Wi_b = (const float*)d_in[7];
    const float* Wh_b = (const float*)d_in[8];
    const float* bi_b = (const float*)d_in[9];
    const float* bh_b = (const float*)d_in[10];
    const float* Wi_d = (const float*)d_in[11];
    const float* Wh_d = (const float*)d_in[12];
    const float* bi_d = (const float*)d_in[13];
    const float* bh_d = (const float*)d_in[14];
    const float* W1_w = (const float*)d_in[15];
    const float* W1_b = (const float*)d_in[16];
    const float* W2_w = (const float*)d_in[17];
    const float* W2_b = (const float*)d_in[18];
    const float* lin_w = (const float*)d_in[19];
    const float* lin_b = (const float*)d_in[20];

    float *gi_f, *gi_b, *gi_demb, *encoded, *outs, *hdec, *w2v, *Mp;
    __nv_bfloat16 *linw3, *outs3;
    int *lastidx;
    cudaGetSymbolAddress((void**)&gi_f,    g_gi_f);
    cudaGetSymbolAddress((void**)&gi_b,    g_gi_b);
    cudaGetSymbolAddress((void**)&gi_demb, g_gi_demb);
    cudaGetSymbolAddress((void**)&encoded, g_encoded);
    cudaGetSymbolAddress((void**)&outs,    g_outs);
    cudaGetSymbolAddress((void**)&hdec,    g_hdec);
    cudaGetSymbolAddress((void**)&w2v,     g_W2v);
    cudaGetSymbolAddress((void**)&Mp,      g_M);
    cudaGetSymbolAddress((void**)&lastidx, g_lastidx);
    cudaGetSymbolAddress((void**)&linw3,   g_linw3);
    cudaGetSymbolAddress((void**)&outs3,   g_outs3);

    cudaFuncSetAttribute(enc_persist, cudaFuncAttributeMaxDynamicSharedMemorySize,
                         ENC_SMEM_FLOATS*sizeof(float));

    init_kernel<<<1, 256>>>(enc_in);                                            // 0
    transpose_all<<<(1114112 + 255)/256, 256>>>(Wh_f, Wh_b, Wi_d, Wh_d, W2_w);  // 1
    convert_split3<<<(Vv*256 + 255)/256, 256>>>(lin_w, linw3, Vv*256, 1);       // 2

    // input projections (embedding gather fused)
    sgemm128<<<dim3(H3/128, Bsz*TE/128), 256>>>(
        embed_W, enc_in, Ee, Wi_f, Ee, 0, bi_f, gi_f, H3, Bsz*TE, H3, Ee);      // 3
    sgemm128<<<dim3(H3/128, Bsz*TE/128), 256>>>(
        embed_W, enc_in, Ee, Wi_b, Ee, 0, bi_b, gi_b, H3, Bsz*TE, H3, Ee);      // 4
    sgemm128<<<dim3(H3/128, Bsz*TD/128), 256>>>(
        embed_W, dec_in, Ee, Wi_d, Ee + 2*Hh, 2*Hh, bi_d, gi_demb, H3, Bsz*TD, H3, Ee); // 5 <- ncu

    // encoder recurrence (persistent)
    enc_persist<<<64, 256, ENC_SMEM_FLOATS*sizeof(float)>>>(bh_f, bh_b);

    // attention precompute
    sgemm128<<<dim3(Hh/128, Bsz*TE/128), 256>>>(
        encoded, nullptr, 2*Hh, w2v, 2*Hh, 0, nullptr, Mp, Hh, Bsz*TE, Hh, 2*Hh);
    s0_kernel<<<64, 256>>>(W2_b);

    // h_init
    sgemm128<<<dim3(2, 1), 256>>>(
        encoded, lastidx, 2*Hh, W1_w, 2*Hh, 0, W1_b, hdec, Hh, Bsz, Hh, 2*Hh);

    // decoder + attention (persistent)
    dec_persist<<<64, 256>>>(bh_d);

    // classifier on tensor cores: three-term split, bf16 HMMA K=768
    convert_split3<<<(Bsz*TD*256 + 255)/256, 256>>>(outs, outs3, Bsz*TD*256, 0);
    cls_hmma<<<dim3(Vv/128, Bsz*TD/128), 256>>>(outs3, linw3, lin_b, (float*)d_out);
}